// round 2
// baseline (speedup 1.0000x reference)
#include <cuda_runtime.h>
#include <cuda_bf16.h>
#include <cstdint>

// ---------------------------------------------------------------------------
// Problem constants
// ---------------------------------------------------------------------------
#define B_  2
#define S_  1024
#define D_  768
#define H_  12
#define DH_ 64
#define M_  64
#define DFF_ 3072
#define NT_ (B_ * S_)          // 2048 tokens
#define QKV_ (3 * D_)          // 2304

// ---------------------------------------------------------------------------
// Scratch (no allocation allowed -> __device__ globals)
// ---------------------------------------------------------------------------
__device__ float g_a   [NT_ * D_];        // LN1 output
__device__ float g_qkv [NT_ * QKV_];      // qkv
__device__ float g_phiq[B_ * H_ * S_ * M_];
__device__ float g_phik[B_ * H_ * S_ * M_];
__device__ float g_attn[NT_ * D_];        // attention out, [token][h*DH+d]
__device__ float g_x1  [NT_ * D_];        // residual stream after attn
__device__ float g_h   [NT_ * D_];        // LN2 output
__device__ float g_ff  [NT_ * DFF_];      // gelu(fc) output

// ---------------------------------------------------------------------------
// LayerNorm: one block per token row (D=768, 256 threads x 3 elems)
// ---------------------------------------------------------------------------
__global__ void ln_kernel(const float* __restrict__ x,
                          const float* __restrict__ g,
                          const float* __restrict__ b,
                          float* __restrict__ o)
{
    int row = blockIdx.x;
    int t   = threadIdx.x;
    const float* xr = x + (size_t)row * D_;

    float v0 = xr[t], v1 = xr[t + 256], v2 = xr[t + 512];
    float s  = v0 + v1 + v2;
    float sq = v0 * v0 + v1 * v1 + v2 * v2;

    #pragma unroll
    for (int off = 16; off; off >>= 1) {
        s  += __shfl_xor_sync(0xffffffffu, s,  off);
        sq += __shfl_xor_sync(0xffffffffu, sq, off);
    }
    __shared__ float red[16];
    int w = t >> 5, l = t & 31;
    if (l == 0) { red[w] = s; red[w + 8] = sq; }
    __syncthreads();
    s = 0.f; sq = 0.f;
    #pragma unroll
    for (int i = 0; i < 8; i++) { s += red[i]; sq += red[8 + i]; }

    const float inv = 1.0f / (float)D_;
    float mean = s * inv;
    float var  = sq * inv - mean * mean;
    float rs   = rsqrtf(var + 1e-5f);

    float* orow = o + (size_t)row * D_;
    orow[t]       = (v0 - mean) * rs * g[t]       + b[t];
    orow[t + 256] = (v1 - mean) * rs * g[t + 256] + b[t + 256];
    orow[t + 512] = (v2 - mean) * rs * g[t + 512] + b[t + 512];
}

// ---------------------------------------------------------------------------
// Generic fp32 GEMM: C[rows x N] = A[rows x K] @ W[K x N] + bias (+res)(+gelu)
// 64x64 tile, BK=16, 256 threads, 4x4 per-thread register block.
// All dims divide evenly for every call site -> no bounds checks.
// ---------------------------------------------------------------------------
__device__ __forceinline__ float gelu_tanh(float x)
{
    float x3 = x * x * x;
    float u  = 0.7978845608028654f * (x + 0.044715f * x3);
    return 0.5f * x * (1.0f + tanhf(u));
}

template<int GELU, int RES>
__global__ void gemm_kernel(const float* __restrict__ A,
                            const float* __restrict__ W,
                            const float* __restrict__ bias,
                            const float* __restrict__ res,
                            float* __restrict__ C,
                            int K, int N)
{
    __shared__ float As[16][68];   // [kk][row], padded
    __shared__ float Ws[16][64];   // [kk][col]

    const int bm = blockIdx.x * 64;
    const int bn = blockIdx.y * 64;
    const int t  = threadIdx.x;
    const int tx = t & 15;
    const int ty = t >> 4;

    float acc[4][4];
    #pragma unroll
    for (int i = 0; i < 4; i++)
        #pragma unroll
        for (int j = 0; j < 4; j++) acc[i][j] = 0.f;

    const int ar = t >> 2, ak = (t & 3) * 4;     // A-tile loader coords
    const int wk = t >> 4, wc = (t & 15) * 4;    // W-tile loader coords
    const float* Aptr = A + (size_t)(bm + ar) * K + ak;
    const float* Wptr = W + (size_t)wk * N + bn + wc;

    for (int k0 = 0; k0 < K; k0 += 16) {
        float4 av = *(const float4*)(Aptr + k0);
        float4 wv = *(const float4*)(Wptr + (size_t)k0 * N);

        __syncthreads();
        As[ak + 0][ar] = av.x;
        As[ak + 1][ar] = av.y;
        As[ak + 2][ar] = av.z;
        As[ak + 3][ar] = av.w;
        *(float4*)&Ws[wk][wc] = wv;
        __syncthreads();

        #pragma unroll
        for (int kk = 0; kk < 16; kk++) {
            float4 a = *(const float4*)&As[kk][ty * 4];
            float4 b = *(const float4*)&Ws[kk][tx * 4];
            float ai[4] = {a.x, a.y, a.z, a.w};
            float bj[4] = {b.x, b.y, b.z, b.w};
            #pragma unroll
            for (int i = 0; i < 4; i++)
                #pragma unroll
                for (int j = 0; j < 4; j++)
                    acc[i][j] = fmaf(ai[i], bj[j], acc[i][j]);
        }
    }

    #pragma unroll
    for (int i = 0; i < 4; i++) {
        int row = bm + ty * 4 + i;
        #pragma unroll
        for (int j = 0; j < 4; j++) {
            int col = bn + tx * 4 + j;
            float v = acc[i][j] + bias[col];
            if (RES)  v += res[(size_t)row * N + col];
            if (GELU) v = gelu_tanh(v);
            C[(size_t)row * N + col] = v;
        }
    }
}

// ---------------------------------------------------------------------------
// FAVOR+ features: phi = exp(x_s @ wfeat^T - 0.5*|x_s|^2) / sqrt(M) + 1e-6
// x_s = (q or k) * DH^-0.25.  One block per (b, h, qk, 32-row s-chunk).
// ---------------------------------------------------------------------------
__global__ void phi_kernel(const float* __restrict__ qkv,
                           const float* __restrict__ wfeat,
                           float* __restrict__ phiq,
                           float* __restrict__ phik)
{
    const int sc = blockIdx.x;            // 0..31 (s chunk)
    const int hy = blockIdx.y;            // 0..23 (h + 12*qk)
    const int b  = blockIdx.z;            // 0..1
    const int h  = hy % H_;
    const int qk = hy / H_;

    __shared__ float wfT[64][65];         // transposed wfeat: [d][m]
    __shared__ float xs[32][64];
    __shared__ float sqs[32];

    const int t = threadIdx.x;

    #pragma unroll
    for (int i = 0; i < 16; i++) {
        int idx = t + i * 256;            // idx = m*64 + d
        wfT[idx & 63][idx >> 6] = wfeat[idx];
    }

    const float scale = 0.3535533905932738f;   // 64^-0.25
    const int s0   = sc * 32;
    const int col0 = qk * D_ + h * DH_;

    #pragma unroll
    for (int i = 0; i < 8; i++) {
        int idx = t + i * 256;
        int sl = idx >> 6, d = idx & 63;
        xs[sl][d] = qkv[(size_t)(b * S_ + s0 + sl) * QKV_ + col0 + d] * scale;
    }
    __syncthreads();

    {   // 0.5 * sum of squares per row: 8 lanes per row
        int sl = t >> 3, p = t & 7;
        float acc = 0.f;
        #pragma unroll
        for (int dd = 0; dd < 8; dd++) {
            float xv = xs[sl][p * 8 + dd];
            acc = fmaf(xv, xv, acc);
        }
        acc += __shfl_xor_sync(0xffffffffu, acc, 1);
        acc += __shfl_xor_sync(0xffffffffu, acc, 2);
        acc += __shfl_xor_sync(0xffffffffu, acc, 4);
        if (p == 0) sqs[sl] = 0.5f * acc;
    }
    __syncthreads();

    float* dst = qk ? phik : phiq;
    #pragma unroll
    for (int i = 0; i < 8; i++) {
        int idx = t + i * 256;
        int sl = idx >> 6, m = idx & 63;
        float acc = 0.f;
        #pragma unroll
        for (int d = 0; d < 64; d++)
            acc = fmaf(xs[sl][d], wfT[d][m], acc);
        float ph = __expf(acc - sqs[sl]) * 0.125f + 1e-6f;
        dst[(size_t)((b * H_ + h) * S_ + s0 + sl) * M_ + m] = ph;
    }
}

// ---------------------------------------------------------------------------
// Causal linear-attention scan. One block per (b,h). 256 threads:
// d = tid>>2 (0..63), mg = tid&3 -> this thread owns kv[m][d], ksum[m] for
// m in [mg*16, mg*16+16). num/den reduced across mg via intra-warp shfl.
// ---------------------------------------------------------------------------
__global__ void scan_kernel(const float* __restrict__ qkv,
                            const float* __restrict__ phiq,
                            const float* __restrict__ phik,
                            float* __restrict__ attn)
{
    const int bh = blockIdx.x;
    const int b  = bh / H_;
    const int h  = bh % H_;
    const int t  = threadIdx.x;
    const int d  = t >> 2;
    const int mg = t & 3;

    float kv[16], ks[16];
    #pragma unroll
    for (int i = 0; i < 16; i++) { kv[i] = 0.f; ks[i] = 0.f; }

    const float* pq = phiq + (size_t)bh * S_ * M_ + mg * 16;
    const float* pk = phik + (size_t)bh * S_ * M_ + mg * 16;
    const float* pv = qkv  + (size_t)b * S_ * QKV_ + 2 * D_ + h * DH_ + d;
    float*       po = attn + (size_t)b * S_ * D_ + h * DH_ + d;

    for (int s = 0; s < S_; s++) {
        const float4* pk4 = (const float4*)pk;
        const float4* pq4 = (const float4*)pq;
        float kr[16], qr[16];
        ((float4*)kr)[0] = pk4[0]; ((float4*)kr)[1] = pk4[1];
        ((float4*)kr)[2] = pk4[2]; ((float4*)kr)[3] = pk4[3];
        ((float4*)qr)[0] = pq4[0]; ((float4*)qr)[1] = pq4[1];
        ((float4*)qr)[2] = pq4[2]; ((float4*)qr)[3] = pq4[3];
        float vv = *pv;

        float num = 0.f, den = 0.f;
        #pragma unroll
        for (int i = 0; i < 16; i++) {
            kv[i] = fmaf(kr[i], vv, kv[i]);
            ks[i] += kr[i];
            num = fmaf(qr[i], kv[i], num);
            den = fmaf(qr[i], ks[i], den);
        }
        num += __shfl_xor_sync(0xffffffffu, num, 1);
        den += __shfl_xor_sync(0xffffffffu, den, 1);
        num += __shfl_xor_sync(0xffffffffu, num, 2);
        den += __shfl_xor_sync(0xffffffffu, den, 2);

        if (mg == 0) po[(size_t)s * D_] = num / den;

        pq += M_; pk += M_; pv += QKV_;
    }
}

// ---------------------------------------------------------------------------
// Launch
// ---------------------------------------------------------------------------
extern "C" void kernel_launch(void* const* d_in, const int* in_sizes, int n_in,
                              void* d_out, int out_size)
{
    const float* x      = (const float*)d_in[0];
    const float* ln1_g  = (const float*)d_in[1];
    const float* ln1_b  = (const float*)d_in[2];
    const float* w_attn = (const float*)d_in[3];
    const float* b_attn = (const float*)d_in[4];
    const float* w_feat = (const float*)d_in[5];
    const float* w_proj = (const float*)d_in[6];
    const float* b_proj = (const float*)d_in[7];
    const float* ln2_g  = (const float*)d_in[8];
    const float* ln2_b  = (const float*)d_in[9];
    const float* w_fc   = (const float*)d_in[10];
    const float* b_fc   = (const float*)d_in[11];
    const float* w_out  = (const float*)d_in[12];
    const float* b_out  = (const float*)d_in[13];
    float* out = (float*)d_out;

    float *a, *qkv, *phiq, *phik, *attn, *x1, *hh, *ff;
    cudaGetSymbolAddress((void**)&a,    g_a);
    cudaGetSymbolAddress((void**)&qkv,  g_qkv);
    cudaGetSymbolAddress((void**)&phiq, g_phiq);
    cudaGetSymbolAddress((void**)&phik, g_phik);
    cudaGetSymbolAddress((void**)&attn, g_attn);
    cudaGetSymbolAddress((void**)&x1,   g_x1);
    cudaGetSymbolAddress((void**)&hh,   g_h);
    cudaGetSymbolAddress((void**)&ff,   g_ff);

    // 1. LN1
    ln_kernel<<<NT_, 256>>>(x, ln1_g, ln1_b, a);

    // 2. qkv = a @ w_attn + b_attn            [2048 x 2304]
    gemm_kernel<0,0><<<dim3(NT_/64, QKV_/64), 256>>>(a, w_attn, b_attn, nullptr, qkv, D_, QKV_);

    // 3. FAVOR+ features
    phi_kernel<<<dim3(S_/32, H_*2, B_), 256>>>(qkv, w_feat, phiq, phik);

    // 4. causal linear-attention scan
    scan_kernel<<<B_*H_, 256>>>(qkv, phiq, phik, attn);

    // 5. x1 = x + attn @ w_proj + b_proj      [2048 x 768]
    gemm_kernel<0,1><<<dim3(NT_/64, D_/64), 256>>>(attn, w_proj, b_proj, x, x1, D_, D_);

    // 6. LN2
    ln_kernel<<<NT_, 256>>>(x1, ln2_g, ln2_b, hh);

    // 7. ff = gelu(h @ w_fc + b_fc)           [2048 x 3072]
    gemm_kernel<1,0><<<dim3(NT_/64, DFF_/64), 256>>>(hh, w_fc, b_fc, nullptr, ff, D_, DFF_);

    // 8. out = x1 + ff @ w_out + b_out        [2048 x 768]
    gemm_kernel<0,1><<<dim3(NT_/64, D_/64), 256>>>(ff, w_out, b_out, x1, out, DFF_, D_);
}

// round 5
// speedup vs baseline: 1.5331x; 1.5331x over previous
#include <cuda_runtime.h>
#include <cuda_bf16.h>
#include <cstdint>

// ---------------------------------------------------------------------------
// Problem constants
// ---------------------------------------------------------------------------
#define B_  2
#define S_  1024
#define D_  768
#define H_  12
#define DH_ 64
#define M_  64
#define DFF_ 3072
#define NT_ (B_ * S_)          // 2048 tokens
#define QKV_ (3 * D_)          // 2304

typedef __nv_bfloat16 bf16;

// ---------------------------------------------------------------------------
// Scratch (__device__ globals; no allocation allowed)
// ---------------------------------------------------------------------------
__device__ bf16  g_a_hi [NT_ * D_];
__device__ bf16  g_a_lo [NT_ * D_];
__device__ float g_qkv  [NT_ * QKV_];
__device__ float g_phiq [B_ * H_ * S_ * M_];
__device__ float g_phik [B_ * H_ * S_ * M_];
__device__ bf16  g_at_hi[NT_ * D_];
__device__ bf16  g_at_lo[NT_ * D_];
__device__ float g_x1   [NT_ * D_];
__device__ bf16  g_h_hi [NT_ * D_];
__device__ bf16  g_h_lo [NT_ * D_];
__device__ bf16  g_ff_hi[NT_ * DFF_];
__device__ bf16  g_ff_lo[NT_ * DFF_];
// transposed, split weights: Wt[n][k] = W[k][n]
__device__ bf16  g_wA_hi[QKV_ * D_];
__device__ bf16  g_wA_lo[QKV_ * D_];
__device__ bf16  g_wP_hi[D_ * D_];
__device__ bf16  g_wP_lo[D_ * D_];
__device__ bf16  g_wF_hi[DFF_ * D_];
__device__ bf16  g_wF_lo[DFF_ * D_];
__device__ bf16  g_wO_hi[D_ * DFF_];
__device__ bf16  g_wO_lo[D_ * DFF_];

// ---------------------------------------------------------------------------
// Small helpers
// ---------------------------------------------------------------------------
__device__ __forceinline__ uint32_t smem_to_u32(const void* p) {
    uint32_t a;
    asm("{ .reg .u64 t; cvta.to.shared.u64 t, %1; cvt.u32.u64 %0, t; }"
        : "=r"(a) : "l"(p));
    return a;
}

__device__ __forceinline__ void split_bf16(float v, bf16& hi, bf16& lo) {
    hi = __float2bfloat16(v);
    lo = __float2bfloat16(v - __bfloat162float(hi));
}

__device__ __forceinline__ float gelu_tanh(float x)
{
    float x3 = x * x * x;
    float u  = 0.7978845608028654f * (x + 0.044715f * x3);
    return 0.5f * x * (1.0f + tanhf(u));
}

// cp.async (sm_80+, legal on plain sm_103 target)
__device__ __forceinline__ void cp_async16(uint32_t saddr, const void* gaddr) {
    asm volatile("cp.async.cg.shared.global [%0], [%1], 16;"
                 :: "r"(saddr), "l"(gaddr));
}
__device__ __forceinline__ void cp_commit() {
    asm volatile("cp.async.commit_group;");
}
template<int N>
__device__ __forceinline__ void cp_wait() {
    asm volatile("cp.async.wait_group %0;" :: "n"(N));
}

// ldmatrix x4 (non-trans)
__device__ __forceinline__ void ldmx4(uint32_t* r, uint32_t addr) {
    asm volatile("ldmatrix.sync.aligned.m8n8.x4.shared.b16 {%0,%1,%2,%3}, [%4];"
                 : "=r"(r[0]), "=r"(r[1]), "=r"(r[2]), "=r"(r[3]) : "r"(addr));
}

// mma.sync m16n8k16 row.col f32 += bf16*bf16
__device__ __forceinline__ void mma16816(float* c, const uint32_t* a,
                                         uint32_t b0, uint32_t b1) {
    asm volatile(
        "mma.sync.aligned.m16n8k16.row.col.f32.bf16.bf16.f32 "
        "{%0,%1,%2,%3}, {%4,%5,%6,%7}, {%8,%9}, {%0,%1,%2,%3};"
        : "+f"(c[0]), "+f"(c[1]), "+f"(c[2]), "+f"(c[3])
        : "r"(a[0]), "r"(a[1]), "r"(a[2]), "r"(a[3]), "r"(b0), "r"(b1));
}

// ---------------------------------------------------------------------------
// LayerNorm -> bf16 hi/lo split output
// ---------------------------------------------------------------------------
__global__ void ln_kernel(const float* __restrict__ x,
                          const float* __restrict__ g,
                          const float* __restrict__ b,
                          bf16* __restrict__ ohi, bf16* __restrict__ olo)
{
    int row = blockIdx.x;
    int t   = threadIdx.x;
    const float* xr = x + (size_t)row * D_;

    float v0 = xr[t], v1 = xr[t + 256], v2 = xr[t + 512];
    float s  = v0 + v1 + v2;
    float sq = v0 * v0 + v1 * v1 + v2 * v2;

    #pragma unroll
    for (int off = 16; off; off >>= 1) {
        s  += __shfl_xor_sync(0xffffffffu, s,  off);
        sq += __shfl_xor_sync(0xffffffffu, sq, off);
    }
    __shared__ float red[16];
    int w = t >> 5, l = t & 31;
    if (l == 0) { red[w] = s; red[w + 8] = sq; }
    __syncthreads();
    s = 0.f; sq = 0.f;
    #pragma unroll
    for (int i = 0; i < 8; i++) { s += red[i]; sq += red[8 + i]; }

    const float inv = 1.0f / (float)D_;
    float mean = s * inv;
    float var  = sq * inv - mean * mean;
    float rs   = rsqrtf(var + 1e-5f);

    size_t base = (size_t)row * D_;
    float vv[3] = {v0, v1, v2};
    #pragma unroll
    for (int i = 0; i < 3; i++) {
        int c = t + i * 256;
        float v = (vv[i] - mean) * rs * g[c] + b[c];
        bf16 hi, lo; split_bf16(v, hi, lo);
        ohi[base + c] = hi; olo[base + c] = lo;
    }
}

// ---------------------------------------------------------------------------
// Weight transpose + bf16 split:  T[n][k] = W[k][n]
// ---------------------------------------------------------------------------
__global__ void wconv_kernel(const float* __restrict__ W,
                             bf16* __restrict__ Thi, bf16* __restrict__ Tlo,
                             int K, int N)
{
    __shared__ float tile[32][33];
    int n0 = blockIdx.x * 32, k0 = blockIdx.y * 32;
    int tx = threadIdx.x, ty = threadIdx.y;
    #pragma unroll
    for (int i = 0; i < 4; i++)
        tile[ty + i * 8][tx] = W[(size_t)(k0 + ty + i * 8) * N + n0 + tx];
    __syncthreads();
    #pragma unroll
    for (int i = 0; i < 4; i++) {
        float v = tile[tx][ty + i * 8];
        size_t idx = (size_t)(n0 + ty + i * 8) * K + k0 + tx;
        bf16 hi, lo; split_bf16(v, hi, lo);
        Thi[idx] = hi; Tlo[idx] = lo;
    }
}

// ---------------------------------------------------------------------------
// HMMA (mma.sync) 3xBF16-split GEMM:
//   C[2048 x N] = Ahi/lo[2048 x K] @ (Bhi/lo[N x K])^T  (+bias)(+res)(+gelu)
// CTA 128x128, BK=32 per chunk, K' = 3K chunk interleave (hi*hi, hi*lo, lo*hi).
// 256 threads = 8 warps, warp tile 32x64 (2 m-tiles x 8 n-tiles of 16x8).
// Smem rows padded to 80B -> conflict-free ldmatrix; cp.async double buffer.
// ---------------------------------------------------------------------------
#define BM 128
#define BN 128
#define BKC 32
#define LDT 40          // padded row length (bf16 elems) = 80 bytes

template<int RES, int GELU, int OUTBF>
__global__ void __launch_bounds__(256)
gemm_mma(const bf16* __restrict__ Ahi, const bf16* __restrict__ Alo,
         const bf16* __restrict__ Bhi, const bf16* __restrict__ Blo,
         const float* __restrict__ bias, const float* __restrict__ res,
         float* __restrict__ Cf, bf16* __restrict__ Chi, bf16* __restrict__ Clo,
         int K, int N)
{
    __shared__ bf16 As[2][BM * LDT];
    __shared__ bf16 Bs[2][BN * LDT];

    const int tid  = threadIdx.x;
    const int lane = tid & 31;
    const int w    = tid >> 5;
    const int wr   = w & 3;        // 4 warps along M (32 rows each)
    const int wc   = w >> 2;       // 2 warps along N (64 cols each)
    const int bm   = blockIdx.x * BM;
    const int bn   = blockIdx.y * BN;

    float acc[2][8][4];
    #pragma unroll
    for (int i = 0; i < 2; i++)
        #pragma unroll
        for (int j = 0; j < 8; j++)
            #pragma unroll
            for (int q = 0; q < 4; q++) acc[i][j][q] = 0.f;

    const int NC = 3 * (K / BKC);

    // loader: thread t covers row (t>>1), 16B segments {0,1} or {2,3}
    const int lrow = tid >> 1;
    const int lseg = (tid & 1) * 2;

    uint32_t sA[2], sB[2];
    sA[0] = smem_to_u32(&As[0][0]); sA[1] = smem_to_u32(&As[1][0]);
    sB[0] = smem_to_u32(&Bs[0][0]); sB[1] = smem_to_u32(&Bs[1][0]);

    auto issue = [&](int c, int st) {
        int which = c % 3;
        int k0 = (c / 3) * BKC;
        const bf16* Asrc = (which == 2) ? Alo : Ahi;
        const bf16* Bsrc = (which == 1) ? Blo : Bhi;
        const bf16* ga = Asrc + (size_t)(bm + lrow) * K + k0 + lseg * 8;
        const bf16* gb = Bsrc + (size_t)(bn + lrow) * K + k0 + lseg * 8;
        uint32_t oa = sA[st] + (uint32_t)(lrow * LDT + lseg * 8) * 2u;
        uint32_t ob = sB[st] + (uint32_t)(lrow * LDT + lseg * 8) * 2u;
        cp_async16(oa,       ga);
        cp_async16(oa + 16u, ga + 8);
        cp_async16(ob,       gb);
        cp_async16(ob + 16u, gb + 8);
    };

    issue(0, 0);
    cp_commit();

    // precomputed ldmatrix lane offsets (bytes)
    const uint32_t aoff = (uint32_t)((wr * 32 + (lane & 15)) * LDT + (lane >> 4) * 8) * 2u;
    const uint32_t boff = (uint32_t)((wc * 64 + (lane & 7) + ((lane >> 4) & 1) * 8) * LDT
                                     + ((lane >> 3) & 1) * 8) * 2u;

    for (int c = 0; c < NC; c++) {
        if (c + 1 < NC) { issue(c + 1, (c + 1) & 1); cp_commit(); cp_wait<1>(); }
        else            { cp_wait<0>(); }
        __syncthreads();

        const int st = c & 1;
        #pragma unroll
        for (int ks = 0; ks < 2; ks++) {
            uint32_t af[2][4], bfr[4][4];
            #pragma unroll
            for (int mt = 0; mt < 2; mt++)
                ldmx4(af[mt], sA[st] + aoff + (uint32_t)(mt * 16 * LDT + ks * 16) * 2u);
            #pragma unroll
            for (int np = 0; np < 4; np++)
                ldmx4(bfr[np], sB[st] + boff + (uint32_t)(np * 16 * LDT + ks * 16) * 2u);
            #pragma unroll
            for (int mt = 0; mt < 2; mt++)
                #pragma unroll
                for (int nt = 0; nt < 8; nt++) {
                    uint32_t b0 = bfr[nt >> 1][(nt & 1) * 2];
                    uint32_t b1 = bfr[nt >> 1][(nt & 1) * 2 + 1];
                    mma16816(acc[mt][nt], af[mt], b0, b1);
                }
        }
        __syncthreads();
    }

    // epilogue: (mt, nt): rows bm+wr*32+mt*16+{g, g+8}, cols bn+wc*64+nt*8+tg*2
    const int g  = lane >> 2;
    const int tg = lane & 3;
    #pragma unroll
    for (int mt = 0; mt < 2; mt++) {
        #pragma unroll
        for (int nt = 0; nt < 8; nt++) {
            int col = bn + wc * 64 + nt * 8 + tg * 2;
            float2 bv = *(const float2*)(bias + col);
            #pragma unroll
            for (int half = 0; half < 2; half++) {
                int row = bm + wr * 32 + mt * 16 + g + half * 8;
                float v0 = acc[mt][nt][half * 2 + 0] + bv.x;
                float v1 = acc[mt][nt][half * 2 + 1] + bv.y;
                size_t idx = (size_t)row * N + col;
                if (RES) {
                    float2 rv = *(const float2*)(res + idx);
                    v0 += rv.x; v1 += rv.y;
                }
                if (GELU) { v0 = gelu_tanh(v0); v1 = gelu_tanh(v1); }
                if (OUTBF) {
                    bf16 h0, l0, h1, l1;
                    split_bf16(v0, h0, l0); split_bf16(v1, h1, l1);
                    *(__nv_bfloat162*)(Chi + idx) = __nv_bfloat162{h0, h1};
                    *(__nv_bfloat162*)(Clo + idx) = __nv_bfloat162{l0, l1};
                } else {
                    *(float2*)(Cf + idx) = make_float2(v0, v1);
                }
            }
        }
    }
}

// ---------------------------------------------------------------------------
// FAVOR+ features (fp32, reads qkv)
// ---------------------------------------------------------------------------
__global__ void phi_kernel(const float* __restrict__ qkv,
                           const float* __restrict__ wfeat,
                           float* __restrict__ phiq,
                           float* __restrict__ phik)
{
    const int sc = blockIdx.x;
    const int hy = blockIdx.y;
    const int b  = blockIdx.z;
    const int h  = hy % H_;
    const int qk = hy / H_;

    __shared__ float wfT[64][65];
    __shared__ float xs[32][64];
    __shared__ float sqs[32];

    const int t = threadIdx.x;

    #pragma unroll
    for (int i = 0; i < 16; i++) {
        int idx = t + i * 256;
        wfT[idx & 63][idx >> 6] = wfeat[idx];
    }

    const float scale = 0.3535533905932738f;
    const int s0   = sc * 32;
    const int col0 = qk * D_ + h * DH_;

    #pragma unroll
    for (int i = 0; i < 8; i++) {
        int idx = t + i * 256;
        int sl = idx >> 6, d = idx & 63;
        xs[sl][d] = qkv[(size_t)(b * S_ + s0 + sl) * QKV_ + col0 + d] * scale;
    }
    __syncthreads();

    {
        int sl = t >> 3, p = t & 7;
        float acc = 0.f;
        #pragma unroll
        for (int dd = 0; dd < 8; dd++) {
            float xv = xs[sl][p * 8 + dd];
            acc = fmaf(xv, xv, acc);
        }
        acc += __shfl_xor_sync(0xffffffffu, acc, 1);
        acc += __shfl_xor_sync(0xffffffffu, acc, 2);
        acc += __shfl_xor_sync(0xffffffffu, acc, 4);
        if (p == 0) sqs[sl] = 0.5f * acc;
    }
    __syncthreads();

    float* dst = qk ? phik : phiq;
    #pragma unroll
    for (int i = 0; i < 8; i++) {
        int idx = t + i * 256;
        int sl = idx >> 6, m = idx & 63;
        float acc = 0.f;
        #pragma unroll
        for (int d = 0; d < 64; d++)
            acc = fmaf(xs[sl][d], wfT[d][m], acc);
        float ph = __expf(acc - sqs[sl]) * 0.125f + 1e-6f;
        dst[(size_t)((b * H_ + h) * S_ + s0 + sl) * M_ + m] = ph;
    }
}

// ---------------------------------------------------------------------------
// Causal linear-attention scan -> bf16 hi/lo output
// ---------------------------------------------------------------------------
__global__ void scan_kernel(const float* __restrict__ qkv,
                            const float* __restrict__ phiq,
                            const float* __restrict__ phik,
                            bf16* __restrict__ ahi, bf16* __restrict__ alo)
{
    const int bh = blockIdx.x;
    const int b  = bh / H_;
    const int h  = bh % H_;
    const int t  = threadIdx.x;
    const int d  = t >> 2;
    const int mg = t & 3;

    float kv[16], ks[16];
    #pragma unroll
    for (int i = 0; i < 16; i++) { kv[i] = 0.f; ks[i] = 0.f; }

    const float* pq = phiq + (size_t)bh * S_ * M_ + mg * 16;
    const float* pk = phik + (size_t)bh * S_ * M_ + mg * 16;
    const float* pv = qkv  + (size_t)b * S_ * QKV_ + 2 * D_ + h * DH_ + d;
    size_t obase = (size_t)b * S_ * D_ + h * DH_ + d;

    for (int s = 0; s < S_; s++) {
        const float4* pk4 = (const float4*)pk;
        const float4* pq4 = (const float4*)pq;
        float kr[16], qr[16];
        ((float4*)kr)[0] = pk4[0]; ((float4*)kr)[1] = pk4[1];
        ((float4*)kr)[2] = pk4[2]; ((float4*)kr)[3] = pk4[3];
        ((float4*)qr)[0] = pq4[0]; ((float4*)qr)[1] = pq4[1];
        ((float4*)qr)[2] = pq4[2]; ((float4*)qr)[3] = pq4[3];
        float vv = *pv;

        float num = 0.f, den = 0.f;
        #pragma unroll
        for (int i = 0; i < 16; i++) {
            kv[i] = fmaf(kr[i], vv, kv[i]);
            ks[i] += kr[i];
            num = fmaf(qr[i], kv[i], num);
            den = fmaf(qr[i], ks[i], den);
        }
        num += __shfl_xor_sync(0xffffffffu, num, 1);
        den += __shfl_xor_sync(0xffffffffu, den, 1);
        num += __shfl_xor_sync(0xffffffffu, num, 2);
        den += __shfl_xor_sync(0xffffffffu, den, 2);

        if (mg == 0) {
            float v = num / den;
            bf16 hi, lo; split_bf16(v, hi, lo);
            ahi[obase + (size_t)s * D_] = hi;
            alo[obase + (size_t)s * D_] = lo;
        }
        pq += M_; pk += M_; pv += QKV_;
    }
}

// ---------------------------------------------------------------------------
// Launch
// ---------------------------------------------------------------------------
extern "C" void kernel_launch(void* const* d_in, const int* in_sizes, int n_in,
                              void* d_out, int out_size)
{
    const float* x      = (const float*)d_in[0];
    const float* ln1_g  = (const float*)d_in[1];
    const float* ln1_b  = (const float*)d_in[2];
    const float* w_attn = (const float*)d_in[3];
    const float* b_attn = (const float*)d_in[4];
    const float* w_feat = (const float*)d_in[5];
    const float* w_proj = (const float*)d_in[6];
    const float* b_proj = (const float*)d_in[7];
    const float* ln2_g  = (const float*)d_in[8];
    const float* ln2_b  = (const float*)d_in[9];
    const float* w_fc   = (const float*)d_in[10];
    const float* b_fc   = (const float*)d_in[11];
    const float* w_out  = (const float*)d_in[12];
    const float* b_out  = (const float*)d_in[13];
    float* out = (float*)d_out;

    bf16 *a_hi, *a_lo, *at_hi, *at_lo, *h_hi, *h_lo, *ff_hi, *ff_lo;
    bf16 *wA_hi, *wA_lo, *wP_hi, *wP_lo, *wF_hi, *wF_lo, *wO_hi, *wO_lo;
    float *qkv, *phiq, *phik, *x1;
    cudaGetSymbolAddress((void**)&a_hi,  g_a_hi);
    cudaGetSymbolAddress((void**)&a_lo,  g_a_lo);
    cudaGetSymbolAddress((void**)&qkv,   g_qkv);
    cudaGetSymbolAddress((void**)&phiq,  g_phiq);
    cudaGetSymbolAddress((void**)&phik,  g_phik);
    cudaGetSymbolAddress((void**)&at_hi, g_at_hi);
    cudaGetSymbolAddress((void**)&at_lo, g_at_lo);
    cudaGetSymbolAddress((void**)&x1,    g_x1);
    cudaGetSymbolAddress((void**)&h_hi,  g_h_hi);
    cudaGetSymbolAddress((void**)&h_lo,  g_h_lo);
    cudaGetSymbolAddress((void**)&ff_hi, g_ff_hi);
    cudaGetSymbolAddress((void**)&ff_lo, g_ff_lo);
    cudaGetSymbolAddress((void**)&wA_hi, g_wA_hi);
    cudaGetSymbolAddress((void**)&wA_lo, g_wA_lo);
    cudaGetSymbolAddress((void**)&wP_hi, g_wP_hi);
    cudaGetSymbolAddress((void**)&wP_lo, g_wP_lo);
    cudaGetSymbolAddress((void**)&wF_hi, g_wF_hi);
    cudaGetSymbolAddress((void**)&wF_lo, g_wF_lo);
    cudaGetSymbolAddress((void**)&wO_hi, g_wO_hi);
    cudaGetSymbolAddress((void**)&wO_lo, g_wO_lo);

    dim3 wblk(32, 8);
    wconv_kernel<<<dim3(QKV_/32, D_/32),  wblk>>>(w_attn, wA_hi, wA_lo, D_,  QKV_);
    wconv_kernel<<<dim3(D_/32,   D_/32),  wblk>>>(w_proj, wP_hi, wP_lo, D_,  D_);
    wconv_kernel<<<dim3(DFF_/32, D_/32),  wblk>>>(w_fc,   wF_hi, wF_lo, D_,  DFF_);
    wconv_kernel<<<dim3(D_/32,  DFF_/32), wblk>>>(w_out,  wO_hi, wO_lo, DFF_, D_);

    // 1. LN1 -> a (hi/lo)
    ln_kernel<<<NT_, 256>>>(x, ln1_g, ln1_b, a_hi, a_lo);

    // 2. qkv = a @ w_attn + b_attn   [2048 x 2304], f32 out
    gemm_mma<0,0,0><<<dim3(NT_/BM, QKV_/BN), 256>>>(
        a_hi, a_lo, wA_hi, wA_lo, b_attn, nullptr, qkv, nullptr, nullptr, D_, QKV_);

    // 3. FAVOR+ features
    phi_kernel<<<dim3(S_/32, H_*2, B_), 256>>>(qkv, w_feat, phiq, phik);

    // 4. causal scan -> attn (hi/lo)
    scan_kernel<<<B_*H_, 256>>>(qkv, phiq, phik, at_hi, at_lo);

    // 5. x1 = x + attn @ w_proj + b_proj   [2048 x 768], f32 out
    gemm_mma<1,0,0><<<dim3(NT_/BM, D_/BN), 256>>>(
        at_hi, at_lo, wP_hi, wP_lo, b_proj, x, x1, nullptr, nullptr, D_, D_);

    // 6. LN2 -> h (hi/lo)
    ln_kernel<<<NT_, 256>>>(x1, ln2_g, ln2_b, h_hi, h_lo);

    // 7. ff = gelu(h @ w_fc + b_fc)   [2048 x 3072], bf16 hi/lo out
    gemm_mma<0,1,1><<<dim3(NT_/BM, DFF_/BN), 256>>>(
        h_hi, h_lo, wF_hi, wF_lo, b_fc, nullptr, nullptr, ff_hi, ff_lo, D_, DFF_);

    // 8. out = x1 + ff @ w_out + b_out   [2048 x 768], f32 out
    gemm_mma<1,0,0><<<dim3(NT_/BM, D_/BN), 256>>>(
        ff_hi, ff_lo, wO_hi, wO_lo, b_out, x1, out, nullptr, nullptr, DFF_, D_);
}

// round 6
// speedup vs baseline: 2.8291x; 1.8453x over previous
#include <cuda_runtime.h>
#include <cuda_bf16.h>
#include <cstdint>

// ---------------------------------------------------------------------------
// Problem constants
// ---------------------------------------------------------------------------
#define B_  2
#define S_  1024
#define D_  768
#define H_  12
#define DH_ 64
#define M_  64
#define DFF_ 3072
#define NT_ (B_ * S_)          // 2048 tokens
#define QKV_ (3 * D_)          // 2304
#define NCH 8                  // scan chunks
#define CHL (S_ / NCH)         // 128 steps per chunk

typedef __nv_bfloat16 bf16;

// ---------------------------------------------------------------------------
// Scratch (__device__ globals; no allocation allowed)
// ---------------------------------------------------------------------------
__device__ bf16  g_a_hi [NT_ * D_];
__device__ bf16  g_a_lo [NT_ * D_];
__device__ float g_qkv  [NT_ * QKV_];
__device__ float g_phiq [B_ * H_ * S_ * M_];
__device__ float g_phik [B_ * H_ * S_ * M_];
__device__ bf16  g_at_hi[NT_ * D_];
__device__ bf16  g_at_lo[NT_ * D_];
__device__ float g_x1   [NT_ * D_];
__device__ bf16  g_h_hi [NT_ * D_];
__device__ bf16  g_h_lo [NT_ * D_];
__device__ bf16  g_ff_hi[NT_ * DFF_];
__device__ bf16  g_ff_lo[NT_ * DFF_];
// scan chunk totals
__device__ float g_kvt  [B_ * H_ * NCH * M_ * DH_];
__device__ float g_kst  [B_ * H_ * NCH * M_];
// transposed, split weights: Wt[n][k] = W[k][n]
__device__ bf16  g_wA_hi[QKV_ * D_];
__device__ bf16  g_wA_lo[QKV_ * D_];
__device__ bf16  g_wP_hi[D_ * D_];
__device__ bf16  g_wP_lo[D_ * D_];
__device__ bf16  g_wF_hi[DFF_ * D_];
__device__ bf16  g_wF_lo[DFF_ * D_];
__device__ bf16  g_wO_hi[D_ * DFF_];
__device__ bf16  g_wO_lo[D_ * DFF_];

// ---------------------------------------------------------------------------
// Small helpers
// ---------------------------------------------------------------------------
__device__ __forceinline__ uint32_t smem_to_u32(const void* p) {
    uint32_t a;
    asm("{ .reg .u64 t; cvta.to.shared.u64 t, %1; cvt.u32.u64 %0, t; }"
        : "=r"(a) : "l"(p));
    return a;
}

__device__ __forceinline__ void split_bf16(float v, bf16& hi, bf16& lo) {
    hi = __float2bfloat16(v);
    lo = __float2bfloat16(v - __bfloat162float(hi));
}

__device__ __forceinline__ float gelu_tanh(float x)
{
    float x3 = x * x * x;
    float u  = 0.7978845608028654f * (x + 0.044715f * x3);
    return 0.5f * x * (1.0f + tanhf(u));
}

__device__ __forceinline__ void cp_async16(uint32_t saddr, const void* gaddr) {
    asm volatile("cp.async.cg.shared.global [%0], [%1], 16;"
                 :: "r"(saddr), "l"(gaddr));
}
__device__ __forceinline__ void cp_commit() {
    asm volatile("cp.async.commit_group;");
}
template<int N>
__device__ __forceinline__ void cp_wait() {
    asm volatile("cp.async.wait_group %0;" :: "n"(N));
}

__device__ __forceinline__ void ldmx4(uint32_t* r, uint32_t addr) {
    asm volatile("ldmatrix.sync.aligned.m8n8.x4.shared.b16 {%0,%1,%2,%3}, [%4];"
                 : "=r"(r[0]), "=r"(r[1]), "=r"(r[2]), "=r"(r[3]) : "r"(addr));
}

__device__ __forceinline__ void mma16816(float* c, const uint32_t* a,
                                         uint32_t b0, uint32_t b1) {
    asm volatile(
        "mma.sync.aligned.m16n8k16.row.col.f32.bf16.bf16.f32 "
        "{%0,%1,%2,%3}, {%4,%5,%6,%7}, {%8,%9}, {%0,%1,%2,%3};"
        : "+f"(c[0]), "+f"(c[1]), "+f"(c[2]), "+f"(c[3])
        : "r"(a[0]), "r"(a[1]), "r"(a[2]), "r"(a[3]), "r"(b0), "r"(b1));
}

// ---------------------------------------------------------------------------
// LayerNorm -> bf16 hi/lo split output
// ---------------------------------------------------------------------------
__global__ void ln_kernel(const float* __restrict__ x,
                          const float* __restrict__ g,
                          const float* __restrict__ b,
                          bf16* __restrict__ ohi, bf16* __restrict__ olo)
{
    int row = blockIdx.x;
    int t   = threadIdx.x;
    const float* xr = x + (size_t)row * D_;

    float v0 = xr[t], v1 = xr[t + 256], v2 = xr[t + 512];
    float s  = v0 + v1 + v2;
    float sq = v0 * v0 + v1 * v1 + v2 * v2;

    #pragma unroll
    for (int off = 16; off; off >>= 1) {
        s  += __shfl_xor_sync(0xffffffffu, s,  off);
        sq += __shfl_xor_sync(0xffffffffu, sq, off);
    }
    __shared__ float red[16];
    int w = t >> 5, l = t & 31;
    if (l == 0) { red[w] = s; red[w + 8] = sq; }
    __syncthreads();
    s = 0.f; sq = 0.f;
    #pragma unroll
    for (int i = 0; i < 8; i++) { s += red[i]; sq += red[8 + i]; }

    const float inv = 1.0f / (float)D_;
    float mean = s * inv;
    float var  = sq * inv - mean * mean;
    float rs   = rsqrtf(var + 1e-5f);

    size_t base = (size_t)row * D_;
    float vv[3] = {v0, v1, v2};
    #pragma unroll
    for (int i = 0; i < 3; i++) {
        int c = t + i * 256;
        float v = (vv[i] - mean) * rs * g[c] + b[c];
        bf16 hi, lo; split_bf16(v, hi, lo);
        ohi[base + c] = hi; olo[base + c] = lo;
    }
}

// ---------------------------------------------------------------------------
// Weight transpose + bf16 split:  T[n][k] = W[k][n]
// ---------------------------------------------------------------------------
__global__ void wconv_kernel(const float* __restrict__ W,
                             bf16* __restrict__ Thi, bf16* __restrict__ Tlo,
                             int K, int N)
{
    __shared__ float tile[32][33];
    int n0 = blockIdx.x * 32, k0 = blockIdx.y * 32;
    int tx = threadIdx.x, ty = threadIdx.y;
    #pragma unroll
    for (int i = 0; i < 4; i++)
        tile[ty + i * 8][tx] = W[(size_t)(k0 + ty + i * 8) * N + n0 + tx];
    __syncthreads();
    #pragma unroll
    for (int i = 0; i < 4; i++) {
        float v = tile[tx][ty + i * 8];
        size_t idx = (size_t)(n0 + ty + i * 8) * K + k0 + tx;
        bf16 hi, lo; split_bf16(v, hi, lo);
        Thi[idx] = hi; Tlo[idx] = lo;
    }
}

// ---------------------------------------------------------------------------
// HMMA 3xBF16-split GEMM, restructured:
// per 32-K slab load {Ahi, Alo, Bhi, Blo} tiles once (dynamic smem, 2 stages),
// fire 3 MMA phases (hi*hi, hi*lo, lo*hi) from resident tiles.
// CTA 128x128, 256 thr = 8 warps, warp tile 32x64.
// ---------------------------------------------------------------------------
#define BM 128
#define BN 128
#define BKC 32
#define LDT 40                         // padded row (bf16) = 80B
#define TILE_ELEMS (BM * LDT)          // per tile
#define TILE_BYTES (TILE_ELEMS * 2)    // 10240
#define STAGE_BYTES (4 * TILE_BYTES)   // 40960
#define GEMM_SMEM (2 * STAGE_BYTES)    // 81920

template<int RES, int GELU, int OUTBF>
__global__ void __launch_bounds__(256)
gemm_mma(const bf16* __restrict__ Ahi, const bf16* __restrict__ Alo,
         const bf16* __restrict__ Bhi, const bf16* __restrict__ Blo,
         const float* __restrict__ bias, const float* __restrict__ res,
         float* __restrict__ Cf, bf16* __restrict__ Chi, bf16* __restrict__ Clo,
         int K, int N)
{
    extern __shared__ char smem[];
    const uint32_t sbase = smem_to_u32(smem);

    const int tid  = threadIdx.x;
    const int lane = tid & 31;
    const int w    = tid >> 5;
    const int wr   = w & 3;
    const int wc   = w >> 2;
    const int bm   = blockIdx.x * BM;
    const int bn   = blockIdx.y * BN;

    float acc[2][8][4];
    #pragma unroll
    for (int i = 0; i < 2; i++)
        #pragma unroll
        for (int j = 0; j < 8; j++)
            #pragma unroll
            for (int q = 0; q < 4; q++) acc[i][j][q] = 0.f;

    const int NC = K / BKC;

    const int lrow = tid >> 1;
    const int lseg = (tid & 1) * 2;
    const uint32_t lsm = (uint32_t)(lrow * LDT + lseg * 8) * 2u;

    auto issue = [&](int c, int st) {
        int k0 = c * BKC;
        const bf16* srcs[4] = {
            Ahi + (size_t)(bm + lrow) * K + k0 + lseg * 8,
            Alo + (size_t)(bm + lrow) * K + k0 + lseg * 8,
            Bhi + (size_t)(bn + lrow) * K + k0 + lseg * 8,
            Blo + (size_t)(bn + lrow) * K + k0 + lseg * 8 };
        uint32_t sb = sbase + (uint32_t)st * STAGE_BYTES + lsm;
        #pragma unroll
        for (int i = 0; i < 4; i++) {
            cp_async16(sb + (uint32_t)i * TILE_BYTES,       srcs[i]);
            cp_async16(sb + (uint32_t)i * TILE_BYTES + 16u, srcs[i] + 8);
        }
    };

    issue(0, 0);
    cp_commit();

    const uint32_t aoff = (uint32_t)((wr * 32 + (lane & 15)) * LDT + (lane >> 4) * 8) * 2u;
    const uint32_t boff = (uint32_t)((wc * 64 + (lane & 7) + ((lane >> 4) & 1) * 8) * LDT
                                     + ((lane >> 3) & 1) * 8) * 2u;

    for (int c = 0; c < NC; c++) {
        if (c + 1 < NC) { issue(c + 1, (c + 1) & 1); cp_commit(); cp_wait<1>(); }
        else            { cp_wait<0>(); }
        __syncthreads();

        const uint32_t st = sbase + (uint32_t)(c & 1) * STAGE_BYTES;
        #pragma unroll
        for (int ks = 0; ks < 2; ks++) {
            const uint32_t ko = (uint32_t)(ks * 16) * 2u;
            uint32_t ah[2][4], al[2][4], bh[4][4], bl[4][4];
            #pragma unroll
            for (int mt = 0; mt < 2; mt++) {
                uint32_t ro = aoff + (uint32_t)(mt * 16 * LDT) * 2u + ko;
                ldmx4(ah[mt], st + ro);
                ldmx4(al[mt], st + TILE_BYTES + ro);
            }
            #pragma unroll
            for (int np = 0; np < 4; np++) {
                uint32_t ro = boff + (uint32_t)(np * 16 * LDT) * 2u + ko;
                ldmx4(bh[np], st + 2u * TILE_BYTES + ro);
                ldmx4(bl[np], st + 3u * TILE_BYTES + ro);
            }
            #pragma unroll
            for (int mt = 0; mt < 2; mt++)
                #pragma unroll
                for (int nt = 0; nt < 8; nt++) {
                    const int np = nt >> 1, half = (nt & 1) * 2;
                    mma16816(acc[mt][nt], ah[mt], bh[np][half], bh[np][half + 1]);
                    mma16816(acc[mt][nt], ah[mt], bl[np][half], bl[np][half + 1]);
                    mma16816(acc[mt][nt], al[mt], bh[np][half], bh[np][half + 1]);
                }
        }
        __syncthreads();
    }

    // epilogue
    const int g  = lane >> 2;
    const int tg = lane & 3;
    #pragma unroll
    for (int mt = 0; mt < 2; mt++) {
        #pragma unroll
        for (int nt = 0; nt < 8; nt++) {
            int col = bn + wc * 64 + nt * 8 + tg * 2;
            float2 bv = *(const float2*)(bias + col);
            #pragma unroll
            for (int half = 0; half < 2; half++) {
                int row = bm + wr * 32 + mt * 16 + g + half * 8;
                float v0 = acc[mt][nt][half * 2 + 0] + bv.x;
                float v1 = acc[mt][nt][half * 2 + 1] + bv.y;
                size_t idx = (size_t)row * N + col;
                if (RES) {
                    float2 rv = *(const float2*)(res + idx);
                    v0 += rv.x; v1 += rv.y;
                }
                if (GELU) { v0 = gelu_tanh(v0); v1 = gelu_tanh(v1); }
                if (OUTBF) {
                    bf16 h0, l0, h1, l1;
                    split_bf16(v0, h0, l0); split_bf16(v1, h1, l1);
                    *(__nv_bfloat162*)(Chi + idx) = __nv_bfloat162{h0, h1};
                    *(__nv_bfloat162*)(Clo + idx) = __nv_bfloat162{l0, l1};
                } else {
                    *(float2*)(Cf + idx) = make_float2(v0, v1);
                }
            }
        }
    }
}

// ---------------------------------------------------------------------------
// FAVOR+ features (fp32, reads qkv)
// ---------------------------------------------------------------------------
__global__ void phi_kernel(const float* __restrict__ qkv,
                           const float* __restrict__ wfeat,
                           float* __restrict__ phiq,
                           float* __restrict__ phik)
{
    const int sc = blockIdx.x;
    const int hy = blockIdx.y;
    const int b  = blockIdx.z;
    const int h  = hy % H_;
    const int qk = hy / H_;

    __shared__ float wfT[64][65];
    __shared__ float xs[32][64];
    __shared__ float sqs[32];

    const int t = threadIdx.x;

    #pragma unroll
    for (int i = 0; i < 16; i++) {
        int idx = t + i * 256;
        wfT[idx & 63][idx >> 6] = wfeat[idx];
    }

    const float scale = 0.3535533905932738f;
    const int s0   = sc * 32;
    const int col0 = qk * D_ + h * DH_;

    #pragma unroll
    for (int i = 0; i < 8; i++) {
        int idx = t + i * 256;
        int sl = idx >> 6, d = idx & 63;
        xs[sl][d] = qkv[(size_t)(b * S_ + s0 + sl) * QKV_ + col0 + d] * scale;
    }
    __syncthreads();

    {
        int sl = t >> 3, p = t & 7;
        float acc = 0.f;
        #pragma unroll
        for (int dd = 0; dd < 8; dd++) {
            float xv = xs[sl][p * 8 + dd];
            acc = fmaf(xv, xv, acc);
        }
        acc += __shfl_xor_sync(0xffffffffu, acc, 1);
        acc += __shfl_xor_sync(0xffffffffu, acc, 2);
        acc += __shfl_xor_sync(0xffffffffu, acc, 4);
        if (p == 0) sqs[sl] = 0.5f * acc;
    }
    __syncthreads();

    float* dst = qk ? phik : phiq;
    #pragma unroll
    for (int i = 0; i < 8; i++) {
        int idx = t + i * 256;
        int sl = idx >> 6, m = idx & 63;
        float acc = 0.f;
        #pragma unroll
        for (int d = 0; d < 64; d++)
            acc = fmaf(xs[sl][d], wfT[d][m], acc);
        float ph = __expf(acc - sqs[sl]) * 0.125f + 1e-6f;
        dst[(size_t)((b * H_ + h) * S_ + s0 + sl) * M_ + m] = ph;
    }
}

// ---------------------------------------------------------------------------
// Scan pass 1: per-(bh, chunk) totals of phik (x) v and phik.
// Thread layout: d = t>>2, mg = t&3 (16 m per thread).
// ---------------------------------------------------------------------------
__global__ void scan_tot_kernel(const float* __restrict__ qkv,
                                const float* __restrict__ phik,
                                float* __restrict__ kvt,
                                float* __restrict__ kst)
{
    const int bc = blockIdx.x;
    const int bh = bc / NCH;
    const int ch = bc % NCH;
    const int b  = bh / H_;
    const int h  = bh % H_;
    const int t  = threadIdx.x;
    const int d  = t >> 2;
    const int mg = t & 3;

    float kv[16], ks[16];
    #pragma unroll
    for (int i = 0; i < 16; i++) { kv[i] = 0.f; ks[i] = 0.f; }

    const int s0 = ch * CHL;
    const float* pk = phik + (size_t)bh * S_ * M_ + (size_t)s0 * M_ + mg * 16;
    const float* pv = qkv  + (size_t)(b * S_ + s0) * QKV_ + 2 * D_ + h * DH_ + d;

    for (int s = 0; s < CHL; s++) {
        const float4* pk4 = (const float4*)pk;
        float kr[16];
        ((float4*)kr)[0] = pk4[0]; ((float4*)kr)[1] = pk4[1];
        ((float4*)kr)[2] = pk4[2]; ((float4*)kr)[3] = pk4[3];
        float vv = *pv;
        #pragma unroll
        for (int i = 0; i < 16; i++) {
            kv[i] = fmaf(kr[i], vv, kv[i]);
            ks[i] += kr[i];
        }
        pk += M_; pv += QKV_;
    }

    size_t base = (size_t)bc * M_ + mg * 16;
    #pragma unroll
    for (int i = 0; i < 16; i++) {
        kvt[(base + i) * DH_ + d] = kv[i];
        if (d == 0) kst[base + i] = ks[i];
    }
}

// ---------------------------------------------------------------------------
// Scan pass 2: local inclusive scan per (bh, chunk), seeded by totals of
// preceding chunks. Output bf16 hi/lo.
// ---------------------------------------------------------------------------
__global__ void scan_kernel(const float* __restrict__ qkv,
                            const float* __restrict__ phiq,
                            const float* __restrict__ phik,
                            const float* __restrict__ kvt,
                            const float* __restrict__ kst,
                            bf16* __restrict__ ahi, bf16* __restrict__ alo)
{
    const int bc = blockIdx.x;
    const int bh = bc / NCH;
    const int ch = bc % NCH;
    const int b  = bh / H_;
    const int h  = bh % H_;
    const int t  = threadIdx.x;
    const int d  = t >> 2;
    const int mg = t & 3;

    float kv[16], ks[16];
    #pragma unroll
    for (int i = 0; i < 16; i++) { kv[i] = 0.f; ks[i] = 0.f; }

    for (int pc = 0; pc < ch; pc++) {
        size_t base = (size_t)(bh * NCH + pc) * M_ + mg * 16;
        #pragma unroll
        for (int i = 0; i < 16; i++) {
            kv[i] += kvt[(base + i) * DH_ + d];
            ks[i] += kst[base + i];
        }
    }

    const int s0 = ch * CHL;
    const float* pq = phiq + (size_t)bh * S_ * M_ + (size_t)s0 * M_ + mg * 16;
    const float* pk = phik + (size_t)bh * S_ * M_ + (size_t)s0 * M_ + mg * 16;
    const float* pv = qkv  + (size_t)(b * S_ + s0) * QKV_ + 2 * D_ + h * DH_ + d;
    size_t obase = (size_t)(b * S_ + s0) * D_ + h * DH_ + d;

    for (int s = 0; s < CHL; s++) {
        const float4* pk4 = (const float4*)pk;
        const float4* pq4 = (const float4*)pq;
        float kr[16], qr[16];
        ((float4*)kr)[0] = pk4[0]; ((float4*)kr)[1] = pk4[1];
        ((float4*)kr)[2] = pk4[2]; ((float4*)kr)[3] = pk4[3];
        ((float4*)qr)[0] = pq4[0]; ((float4*)qr)[1] = pq4[1];
        ((float4*)qr)[2] = pq4[2]; ((float4*)qr)[3] = pq4[3];
        float vv = *pv;

        float num = 0.f, den = 0.f;
        #pragma unroll
        for (int i = 0; i < 16; i++) {
            kv[i] = fmaf(kr[i], vv, kv[i]);
            ks[i] += kr[i];
            num = fmaf(qr[i], kv[i], num);
            den = fmaf(qr[i], ks[i], den);
        }
        num += __shfl_xor_sync(0xffffffffu, num, 1);
        den += __shfl_xor_sync(0xffffffffu, den, 1);
        num += __shfl_xor_sync(0xffffffffu, num, 2);
        den += __shfl_xor_sync(0xffffffffu, den, 2);

        if (mg == 0) {
            float v = num / den;
            bf16 hi, lo; split_bf16(v, hi, lo);
            ahi[obase] = hi;
            alo[obase] = lo;
        }
        pq += M_; pk += M_; pv += QKV_; obase += D_;
    }
}

// ---------------------------------------------------------------------------
// Launch
// ---------------------------------------------------------------------------
extern "C" void kernel_launch(void* const* d_in, const int* in_sizes, int n_in,
                              void* d_out, int out_size)
{
    const float* x      = (const float*)d_in[0];
    const float* ln1_g  = (const float*)d_in[1];
    const float* ln1_b  = (const float*)d_in[2];
    const float* w_attn = (const float*)d_in[3];
    const float* b_attn = (const float*)d_in[4];
    const float* w_feat = (const float*)d_in[5];
    const float* w_proj = (const float*)d_in[6];
    const float* b_proj = (const float*)d_in[7];
    const float* ln2_g  = (const float*)d_in[8];
    const float* ln2_b  = (const float*)d_in[9];
    const float* w_fc   = (const float*)d_in[10];
    const float* b_fc   = (const float*)d_in[11];
    const float* w_out  = (const float*)d_in[12];
    const float* b_out  = (const float*)d_in[13];
    float* out = (float*)d_out;

    bf16 *a_hi, *a_lo, *at_hi, *at_lo, *h_hi, *h_lo, *ff_hi, *ff_lo;
    bf16 *wA_hi, *wA_lo, *wP_hi, *wP_lo, *wF_hi, *wF_lo, *wO_hi, *wO_lo;
    float *qkv, *phiq, *phik, *x1, *kvt, *kst;
    cudaGetSymbolAddress((void**)&a_hi,  g_a_hi);
    cudaGetSymbolAddress((void**)&a_lo,  g_a_lo);
    cudaGetSymbolAddress((void**)&qkv,   g_qkv);
    cudaGetSymbolAddress((void**)&phiq,  g_phiq);
    cudaGetSymbolAddress((void**)&phik,  g_phik);
    cudaGetSymbolAddress((void**)&at_hi, g_at_hi);
    cudaGetSymbolAddress((void**)&at_lo, g_at_lo);
    cudaGetSymbolAddress((void**)&x1,    g_x1);
    cudaGetSymbolAddress((void**)&h_hi,  g_h_hi);
    cudaGetSymbolAddress((void**)&h_lo,  g_h_lo);
    cudaGetSymbolAddress((void**)&ff_hi, g_ff_hi);
    cudaGetSymbolAddress((void**)&ff_lo, g_ff_lo);
    cudaGetSymbolAddress((void**)&kvt,   g_kvt);
    cudaGetSymbolAddress((void**)&kst,   g_kst);
    cudaGetSymbolAddress((void**)&wA_hi, g_wA_hi);
    cudaGetSymbolAddress((void**)&wA_lo, g_wA_lo);
    cudaGetSymbolAddress((void**)&wP_hi, g_wP_hi);
    cudaGetSymbolAddress((void**)&wP_lo, g_wP_lo);
    cudaGetSymbolAddress((void**)&wF_hi, g_wF_hi);
    cudaGetSymbolAddress((void**)&wF_lo, g_wF_lo);
    cudaGetSymbolAddress((void**)&wO_hi, g_wO_hi);
    cudaGetSymbolAddress((void**)&wO_lo, g_wO_lo);

    cudaFuncSetAttribute(gemm_mma<0,0,0>, cudaFuncAttributeMaxDynamicSharedMemorySize, GEMM_SMEM);
    cudaFuncSetAttribute(gemm_mma<1,0,0>, cudaFuncAttributeMaxDynamicSharedMemorySize, GEMM_SMEM);
    cudaFuncSetAttribute(gemm_mma<0,1,1>, cudaFuncAttributeMaxDynamicSharedMemorySize, GEMM_SMEM);

    dim3 wblk(32, 8);
    wconv_kernel<<<dim3(QKV_/32, D_/32),  wblk>>>(w_attn, wA_hi, wA_lo, D_,  QKV_);
    wconv_kernel<<<dim3(D_/32,   D_/32),  wblk>>>(w_proj, wP_hi, wP_lo, D_,  D_);
    wconv_kernel<<<dim3(DFF_/32, D_/32),  wblk>>>(w_fc,   wF_hi, wF_lo, D_,  DFF_);
    wconv_kernel<<<dim3(D_/32,  DFF_/32), wblk>>>(w_out,  wO_hi, wO_lo, DFF_, D_);

    // 1. LN1 -> a (hi/lo)
    ln_kernel<<<NT_, 256>>>(x, ln1_g, ln1_b, a_hi, a_lo);

    // 2. qkv = a @ w_attn + b_attn   [2048 x 2304], f32 out
    gemm_mma<0,0,0><<<dim3(NT_/BM, QKV_/BN), 256, GEMM_SMEM>>>(
        a_hi, a_lo, wA_hi, wA_lo, b_attn, nullptr, qkv, nullptr, nullptr, D_, QKV_);

    // 3. FAVOR+ features
    phi_kernel<<<dim3(S_/32, H_*2, B_), 256>>>(qkv, w_feat, phiq, phik);

    // 4. chunked causal scan -> attn (hi/lo)
    scan_tot_kernel<<<B_*H_*NCH, 256>>>(qkv, phik, kvt, kst);
    scan_kernel<<<B_*H_*NCH, 256>>>(qkv, phiq, phik, kvt, kst, at_hi, at_lo);

    // 5. x1 = x + attn @ w_proj + b_proj   [2048 x 768], f32 out
    gemm_mma<1,0,0><<<dim3(NT_/BM, D_/BN), 256, GEMM_SMEM>>>(
        at_hi, at_lo, wP_hi, wP_lo, b_proj, x, x1, nullptr, nullptr, D_, D_);

    // 6. LN2 -> h (hi/lo)
    ln_kernel<<<NT_, 256>>>(x1, ln2_g, ln2_b, h_hi, h_lo);

    // 7. ff = gelu(h @ w_fc + b_fc)   [2048 x 3072], bf16 hi/lo out
    gemm_mma<0,1,1><<<dim3(NT_/BM, DFF_/BN), 256, GEMM_SMEM>>>(
        h_hi, h_lo, wF_hi, wF_lo, b_fc, nullptr, nullptr, ff_hi, ff_lo, D_, DFF_);

    // 8. out = x1 + ff @ w_out + b_out   [2048 x 768], f32 out
    gemm_mma<1,0,0><<<dim3(NT_/BM, D_/BN), 256, GEMM_SMEM>>>(
        ff_hi, ff_lo, wO_hi, wO_lo, b_out, x1, out, nullptr, nullptr, DFF_, D_);
}